// round 5
// baseline (speedup 1.0000x reference)
#include <cuda_runtime.h>
#include <cuda_bf16.h>

#define BB 512
#define SS 1024
#define TT 64

typedef unsigned long long u64;

// ---- packed f32x2 helpers (Blackwell FFMA2 path) ----
__device__ __forceinline__ u64 fma2(u64 a, u64 b, u64 c) {
    u64 d;
    asm("fma.rn.f32x2 %0, %1, %2, %3;" : "=l"(d) : "l"(a), "l"(b), "l"(c));
    return d;
}
__device__ __forceinline__ u64 add2(u64 a, u64 b) {
    u64 d;
    asm("add.rn.f32x2 %0, %1, %2;" : "=l"(d) : "l"(a), "l"(b));
    return d;
}
__device__ __forceinline__ u64 pack2(float lo, float hi) {
    u64 d;
    asm("mov.b64 %0, {%1, %2};" : "=l"(d) : "f"(lo), "f"(hi));
    return d;
}
__device__ __forceinline__ void unpack2(u64 v, float& lo, float& hi) {
    asm("mov.b64 {%0, %1}, %2;" : "=f"(lo), "=f"(hi) : "l"(v));
}

// mask dtype modes
#define MM_I32 0
#define MM_F32 1
#define MM_U8  2

__device__ __forceinline__ int mask_at(const void* m, long long idx, int mode) {
    if (mode == MM_I32) return ((const int*)m)[idx] != 0;
    if (mode == MM_F32) return ((const float*)m)[idx] != 0.0f;
    return ((const unsigned char*)m)[idx] != 0;
}

__global__ __launch_bounds__(64)
void crf_loss_kernel(const int* __restrict__ tags,
                     const void* __restrict__ mask,
                     const float* __restrict__ emit,
                     const float* __restrict__ trans,
                     float* __restrict__ out) {
    __shared__ __align__(16) float p_s[2][TT];
    __shared__ float wm_s[2];
    __shared__ float red_s[2];
    __shared__ int   lred[2];
    __shared__ float tsred[2];

    const int b    = blockIdx.x;
    const int tp   = threadIdx.x;     // owned t' column, 0..63
    const int wid  = tp >> 5;
    const int lane = tp & 31;

    const float* emitb = emit + (size_t)b * SS * TT;
    const int*   tagsb = tags + b * SS;

    // ---- decode mask storage dtype from first word (mask[0,0..] are 1s) ----
    const int w0 = ((const int*)mask)[0];
    const int mmode = (w0 == 1) ? MM_I32 : ((w0 == 0x3F800000) ? MM_F32 : MM_U8);

    // ---- sequence length = popcount of prefix mask row ----
    int cnt = 0;
    for (int s = tp; s < SS; s += 64)
        cnt += mask_at(mask, (long long)b * SS + s, mmode);
    #pragma unroll
    for (int o = 16; o; o >>= 1) cnt += __shfl_xor_sync(0xFFFFFFFFu, cnt, o);
    if (lane == 0) lred[wid] = cnt;
    __syncthreads();
    const int len = lred[0] + lred[1];

    // ---- total_score: sum of emit[s, tag_s] + trans[tag_{s-1}, tag_s] over s < len ----
    float ts = 0.0f;
    for (int s = tp; s < len; s += 64) {
        int tg = tagsb[s];
        ts += emitb[(size_t)s * TT + tg];
        if (s > 0) ts += trans[tagsb[s - 1] * TT + tg];
    }
    #pragma unroll
    for (int o = 16; o; o >>= 1) ts += __shfl_xor_sync(0xFFFFFFFFu, ts, o);
    if (lane == 0) tsred[wid] = ts;

    // ---- load E column into registers, packed over t pairs ----
    u64 E2[32];
    #pragma unroll
    for (int j = 0; j < 32; j++) {
        float lo = __expf(trans[(2 * j)     * TT + tp]);
        float hi = __expf(trans[(2 * j + 1) * TT + tp]);
        E2[j] = pack2(lo, hi);
    }

    // ---- init: d0 = emit[b, 0, tp]; exact block max for m0 ----
    float d = emitb[tp];
    {
        float wm = d;
        #pragma unroll
        for (int o = 16; o; o >>= 1) wm = fmaxf(wm, __shfl_xor_sync(0xFFFFFFFFu, wm, o));
        if (lane == 0) wm_s[wid] = wm;
    }
    __syncthreads();
    const float ts_total = tsred[0] + tsred[1];
    float m_use = fmaxf(wm_s[0], wm_s[1]);   // m baked into p we are about to write
    float mb    = m_use;                     // m baked into current (readable) p buffer
    p_s[0][tp] = __expf(d - m_use);
    __syncthreads();                         // publish p_s[0]

    // ---- emit prefetch ring, distance 4 ----
    float e_r0 = (1 < len) ? emitb[(size_t)1 * TT + tp] : 0.0f;
    float e_r1 = (2 < len) ? emitb[(size_t)2 * TT + tp] : 0.0f;
    float e_r2 = (3 < len) ? emitb[(size_t)3 * TT + tp] : 0.0f;
    float e_r3 = (4 < len) ? emitb[(size_t)4 * TT + tp] : 0.0f;

    int buf = 0;
    bool pending = false;

    for (int s = 1; s < len; s++) {
        // consume last update's per-warp maxima (lag-1)
        if (pending) { m_use = fmaxf(wm_s[0], wm_s[1]); pending = false; }

        // off-critical-path scale: exp(mb + e - m_use), ready before acc
        float sc = __expf(mb + e_r0 - m_use);

        // acc[tp] = sum_t p[t] * E[t][tp] : 8 chains of depth 4
        const ulonglong2* pp = (const ulonglong2*)p_s[buf];
        u64 a0 = 0ull, a1 = 0ull, a2 = 0ull, a3 = 0ull;
        u64 a4 = 0ull, a5 = 0ull, a6 = 0ull, a7 = 0ull;
        #pragma unroll
        for (int j = 0; j < 32; j += 8) {
            ulonglong2 v0 = pp[(j >> 1)];
            ulonglong2 v1 = pp[(j >> 1) + 1];
            ulonglong2 v2 = pp[(j >> 1) + 2];
            ulonglong2 v3 = pp[(j >> 1) + 3];
            a0 = fma2(v0.x, E2[j],     a0);
            a1 = fma2(v0.y, E2[j + 1], a1);
            a2 = fma2(v1.x, E2[j + 2], a2);
            a3 = fma2(v1.y, E2[j + 3], a3);
            a4 = fma2(v2.x, E2[j + 4], a4);
            a5 = fma2(v2.y, E2[j + 5], a5);
            a6 = fma2(v3.x, E2[j + 6], a6);
            a7 = fma2(v3.y, E2[j + 7], a7);
        }
        u64 t0 = add2(a0, a1);
        u64 t1 = add2(a2, a3);
        u64 t2 = add2(a4, a5);
        u64 t3 = add2(a6, a7);
        u64 u0 = add2(t0, t1);
        u64 u1 = add2(t2, t3);
        u64 tt = add2(u0, u1);
        float flo, fhi;
        unpack2(tt, flo, fhi);
        float acc = flo + fhi;

        // critical path: acc -> one FMUL -> STS
        p_s[buf ^ 1][tp] = acc * sc;

        // true d (consumed only on update steps and at the end)
        d = mb + __logf(acc) + e_r0;

        // refresh normalizer every 8 steps (consumed lag-1)
        if ((s & 7) == 0) {
            float wm = d;
            #pragma unroll
            for (int o = 16; o; o >>= 1) wm = fmaxf(wm, __shfl_xor_sync(0xFFFFFFFFu, wm, o));
            if (lane == 0) wm_s[wid] = wm;
            pending = true;
        }

        __syncthreads();

        mb = m_use;
        buf ^= 1;

        // rotate prefetch ring
        e_r0 = e_r1; e_r1 = e_r2; e_r2 = e_r3;
        e_r3 = (s + 4 < len) ? emitb[(size_t)(s + 4) * TT + tp] : 0.0f;
    }

    // ---- log_z = m_use + log(sum exp(d - m_use)); d-m_use bounded ~[-15, +50], fp32-safe ----
    float ex = __expf(d - m_use);
    #pragma unroll
    for (int o = 16; o; o >>= 1) ex += __shfl_xor_sync(0xFFFFFFFFu, ex, o);
    if (lane == 0) red_s[wid] = ex;
    __syncthreads();
    if (tp == 0) {
        float logz = m_use + __logf(red_s[0] + red_s[1]);
        out[b] = logz - ts_total;   // -(total_score - log_z)
    }
}

extern "C" void kernel_launch(void* const* d_in, const int* in_sizes, int n_in,
                              void* d_out, int out_size) {
    const int*   tags  = (const int*)d_in[0];
    const void*  mask  = d_in[1];
    const float* emit  = (const float*)d_in[2];
    const float* trans = (const float*)d_in[3];
    float* out = (float*)d_out;
    (void)in_sizes; (void)n_in; (void)out_size;

    crf_loss_kernel<<<BB, 64>>>(tags, mask, emit, trans, out);
}

// round 8
// speedup vs baseline: 1.9887x; 1.9887x over previous
#include <cuda_runtime.h>
#include <cuda_bf16.h>

#define BB 512
#define SS 1024
#define TT 64

typedef unsigned long long u64;

// ---- packed f32x2 helpers (Blackwell FFMA2 path) ----
__device__ __forceinline__ u64 fma2(u64 a, u64 b, u64 c) {
    u64 d;
    asm("fma.rn.f32x2 %0, %1, %2, %3;" : "=l"(d) : "l"(a), "l"(b), "l"(c));
    return d;
}
__device__ __forceinline__ u64 add2(u64 a, u64 b) {
    u64 d;
    asm("add.rn.f32x2 %0, %1, %2;" : "=l"(d) : "l"(a), "l"(b));
    return d;
}
__device__ __forceinline__ u64 pack2(float lo, float hi) {
    u64 d;
    asm("mov.b64 %0, {%1, %2};" : "=l"(d) : "f"(lo), "f"(hi));
    return d;
}
__device__ __forceinline__ void unpack2(u64 v, float& lo, float& hi) {
    asm("mov.b64 {%0, %1}, %2;" : "=f"(lo), "=f"(hi) : "l"(v));
}

// mask dtype modes
#define MM_I32 0
#define MM_F32 1
#define MM_U8  2

__device__ __forceinline__ int mask_at(const void* m, long long idx, int mode) {
    if (mode == MM_I32) return ((const int*)m)[idx] != 0;
    if (mode == MM_F32) return ((const float*)m)[idx] != 0.0f;
    return ((const unsigned char*)m)[idx] != 0;
}

__global__ __launch_bounds__(64)
void crf_loss_kernel(const int* __restrict__ tags,
                     const void* __restrict__ mask,
                     const float* __restrict__ emit,
                     const float* __restrict__ trans,
                     float* __restrict__ out) {
    __shared__ __align__(16) float p_s[2][TT];
    __shared__ float wm_s[2];
    __shared__ float red_s[2];
    __shared__ int   lred[2];
    __shared__ float tsred[2];

    const int b    = blockIdx.x;
    const int tp   = threadIdx.x;     // owned t' column, 0..63
    const int wid  = tp >> 5;
    const int lane = tp & 31;

    const float* emitb = emit + (size_t)b * SS * TT;
    const int*   tagsb = tags + b * SS;

    // ---- decode mask storage dtype from first word (mask[0,0..] are 1s) ----
    const int w0 = ((const int*)mask)[0];
    const int mmode = (w0 == 1) ? MM_I32 : ((w0 == 0x3F800000) ? MM_F32 : MM_U8);

    // ---- sequence length = popcount of prefix mask row ----
    int cnt = 0;
    for (int s = tp; s < SS; s += 64)
        cnt += mask_at(mask, (long long)b * SS + s, mmode);
    #pragma unroll
    for (int o = 16; o; o >>= 1) cnt += __shfl_xor_sync(0xFFFFFFFFu, cnt, o);
    if (lane == 0) lred[wid] = cnt;
    __syncthreads();
    const int len = lred[0] + lred[1];

    // ---- total_score: sum of emit[s, tag_s] + trans[tag_{s-1}, tag_s] over s < len ----
    float ts = 0.0f;
    for (int s = tp; s < len; s += 64) {
        int tg = tagsb[s];
        ts += emitb[(size_t)s * TT + tg];
        if (s > 0) ts += trans[tagsb[s - 1] * TT + tg];
    }
    #pragma unroll
    for (int o = 16; o; o >>= 1) ts += __shfl_xor_sync(0xFFFFFFFFu, ts, o);
    if (lane == 0) tsred[wid] = ts;

    // ---- load E column into registers, packed over t pairs ----
    u64 E2[32];
    #pragma unroll
    for (int j = 0; j < 32; j++) {
        float lo = __expf(trans[(2 * j)     * TT + tp]);
        float hi = __expf(trans[(2 * j + 1) * TT + tp]);
        E2[j] = pack2(lo, hi);
    }

    // ---- init: d0 = emit[b, 0, tp]; exact block max for m0 ----
    float d = emitb[tp];
    {
        float wm = d;
        #pragma unroll
        for (int o = 16; o; o >>= 1) wm = fmaxf(wm, __shfl_xor_sync(0xFFFFFFFFu, wm, o));
        if (lane == 0) wm_s[wid] = wm;
    }
    __syncthreads();
    const float ts_total = tsred[0] + tsred[1];
    float m_use = fmaxf(wm_s[0], wm_s[1]);   // m baked into p we are about to write
    float mb    = m_use;                     // m baked into current (readable) p buffer
    p_s[0][tp] = __expf(d - m_use);
    __syncthreads();                         // publish p_s[0]

    // ---- TRUE distance-8 emit prefetch ring: slot k holds emit for step s with (s-1)&7 == k ----
    float e_buf[8];
    #pragma unroll
    for (int i = 0; i < 8; i++)
        e_buf[i] = (1 + i < len) ? emitb[(size_t)(1 + i) * TT + tp] : 0.0f;

    int buf = 0;
    bool pending = false;

    // one step of the recurrence; kk = (s-1)&7 (static inside unrolled loop)
    #define CRF_STEP(S, KK, PREFETCH, DO_MAX)                                        \
    {                                                                                \
        if (pending) { m_use = fmaxf(wm_s[0], wm_s[1]); pending = false; }           \
        float e = e_buf[(KK)];                                                       \
        float sc = __expf(mb + e - m_use);                                           \
        const ulonglong2* pp = (const ulonglong2*)p_s[buf];                          \
        u64 a0 = 0ull, a1 = 0ull, a2 = 0ull, a3 = 0ull;                              \
        u64 a4 = 0ull, a5 = 0ull, a6 = 0ull, a7 = 0ull;                              \
        _Pragma("unroll")                                                            \
        for (int j = 0; j < 32; j += 8) {                                            \
            ulonglong2 v0 = pp[(j >> 1)];                                            \
            ulonglong2 v1 = pp[(j >> 1) + 1];                                        \
            ulonglong2 v2 = pp[(j >> 1) + 2];                                        \
            ulonglong2 v3 = pp[(j >> 1) + 3];                                        \
            a0 = fma2(v0.x, E2[j],     a0);                                          \
            a1 = fma2(v0.y, E2[j + 1], a1);                                          \
            a2 = fma2(v1.x, E2[j + 2], a2);                                          \
            a3 = fma2(v1.y, E2[j + 3], a3);                                          \
            a4 = fma2(v2.x, E2[j + 4], a4);                                          \
            a5 = fma2(v2.y, E2[j + 5], a5);                                          \
            a6 = fma2(v3.x, E2[j + 6], a6);                                          \
            a7 = fma2(v3.y, E2[j + 7], a7);                                          \
        }                                                                            \
        u64 t0 = add2(a0, a1);                                                       \
        u64 t1 = add2(a2, a3);                                                       \
        u64 t2 = add2(a4, a5);                                                       \
        u64 t3 = add2(a6, a7);                                                       \
        u64 u0 = add2(t0, t1);                                                       \
        u64 u1 = add2(t2, t3);                                                       \
        u64 tt = add2(u0, u1);                                                       \
        float flo, fhi;                                                              \
        unpack2(tt, flo, fhi);                                                       \
        float acc = flo + fhi;                                                       \
        p_s[buf ^ 1][tp] = acc * sc;         /* critical path: acc -> FMUL -> STS */ \
        d = mb + __logf(acc) + e;                                                    \
        if (PREFETCH)                                                                \
            e_buf[(KK)] = ((S) + 8 < len) ? emitb[(size_t)((S) + 8) * TT + tp] : 0.0f;\
        if (DO_MAX) {                                                                \
            float wm = d;                                                            \
            _Pragma("unroll")                                                        \
            for (int o = 16; o; o >>= 1)                                             \
                wm = fmaxf(wm, __shfl_xor_sync(0xFFFFFFFFu, wm, o));                 \
            if (lane == 0) wm_s[wid] = wm;                                           \
            pending = true;                                                          \
        }                                                                            \
        __syncthreads();                                                             \
        mb = m_use;                                                                  \
        buf ^= 1;                                                                    \
    }

    int s = 1;
    // main loop: 8 steps per iteration; s always ≡ 1 (mod 8) here, so slot k is static
    for (; s + 8 <= len; s += 8) {
        CRF_STEP(s + 0, 0, true, false)
        CRF_STEP(s + 1, 1, true, false)
        CRF_STEP(s + 2, 2, true, false)
        CRF_STEP(s + 3, 3, true, false)
        CRF_STEP(s + 4, 4, true, false)
        CRF_STEP(s + 5, 5, true, false)
        CRF_STEP(s + 6, 6, true, false)
        CRF_STEP(s + 7, 7, true, true)   // s+7 ≡ 0 (mod 8): refresh normalizer
    }
    // tail: dynamic slot, no prefetch needed
    for (; s < len; s++) {
        CRF_STEP(s, (s - 1) & 7, false, false)
    }
    #undef CRF_STEP

    // ---- log_z = m_use + log(sum exp(d - m_use)); bounded drift (<=8 steps since refresh) ----
    float ex = __expf(d - m_use);
    #pragma unroll
    for (int o = 16; o; o >>= 1) ex += __shfl_xor_sync(0xFFFFFFFFu, ex, o);
    if (lane == 0) red_s[wid] = ex;
    __syncthreads();
    if (tp == 0) {
        float logz = m_use + __logf(red_s[0] + red_s[1]);
        out[b] = logz - ts_total;   // -(total_score - log_z)
    }
}

extern "C" void kernel_launch(void* const* d_in, const int* in_sizes, int n_in,
                              void* d_out, int out_size) {
    const int*   tags  = (const int*)d_in[0];
    const void*  mask  = d_in[1];
    const float* emit  = (const float*)d_in[2];
    const float* trans = (const float*)d_in[3];
    float* out = (float*)d_out;
    (void)in_sizes; (void)n_in; (void)out_size;

    crf_loss_kernel<<<BB, 64>>>(tags, mask, emit, trans, out);
}